// round 16
// baseline (speedup 1.0000x reference)
#include <cuda_runtime.h>
#include <cuda_bf16.h>
#include <cstdint>

#define B_   4
#define C_   64
#define W_   128
#define H_   128
#define O_   64
#define K2C  9
#define OFFC 18
#define NOFF 24
#define HW   (H_*W_)
#define CP_  (C_/2)

__device__ __align__(16) uint32_t g_wq_hi[K2C * 4 * O_ * 8];
__device__ __align__(16) uint32_t g_wq_lo[K2C * 4 * O_ * 8];
__device__ __align__(16) uint32_t g_wo_hi[K2C * 4 * NOFF * 8];
__device__ __align__(16) uint32_t g_wo_lo[K2C * 4 * NOFF * 8];
__device__ __align__(16) float2   g_xp[B_ * CP_ * HW];        // [b][cp][h][w]

__device__ __forceinline__ void mma_bf16(float* d, const uint32_t* a,
                                         const uint32_t* b) {
    asm volatile(
        "mma.sync.aligned.m16n8k16.row.col.f32.bf16.bf16.f32 "
        "{%0,%1,%2,%3}, {%4,%5,%6,%7}, {%8,%9}, {%0,%1,%2,%3};"
        : "+f"(d[0]), "+f"(d[1]), "+f"(d[2]), "+f"(d[3])
        : "r"(a[0]), "r"(a[1]), "r"(a[2]), "r"(a[3]),
          "r"(b[0]), "r"(b[1]));
}

__device__ __forceinline__ void split_store(uint32_t* hi, uint32_t* lo,
                                            float s0, float s1) {
    float2 sv = make_float2(s0, s1);
    __nv_bfloat162 h2 = __float22bfloat162_rn(sv);
    float2 hv = make_float2(__bfloat162float(h2.x), __bfloat162float(h2.y));
    __nv_bfloat162 l2 = __float22bfloat162_rn(make_float2(sv.x - hv.x, sv.y - hv.y));
    *hi = *reinterpret_cast<uint32_t*>(&h2);
    *lo = *reinterpret_cast<uint32_t*>(&l2);
}

// ---------------------------------------------------------------------------
// Kernel 1: merged prep — x channel-pair pack (float4 granularity) + both
// weight tensors (bf16 hi/lo split, [k2][q][o][chpair]).
// ---------------------------------------------------------------------------
#define NX4  (B_ * CP_ * HW / 4)
#define NDCN (K2C * 4 * O_ * 8)
#define NOFFW (K2C * 4 * NOFF * 8)

__global__ void prep_kernel(const float* __restrict__ x,
                            const float* __restrict__ w_dcn,
                            const float* __restrict__ w_off)
{
    int i = blockIdx.x * 256 + threadIdx.x;
    if (i < NX4) {
        int b  = i / (CP_ * HW / 4);
        int r  = i % (CP_ * HW / 4);
        int cp = r / (HW / 4);
        int s4 = (r % (HW / 4)) * 4;
        const float* base = x + ((size_t)(b * C_ + 2 * cp)) * HW + s4;
        float4 a = __ldg((const float4*)base);
        float4 c = __ldg((const float4*)(base + HW));
        float2* dst = g_xp + ((size_t)(b * CP_ + cp)) * HW + s4;
        *(float4*)(dst)     = make_float4(a.x, c.x, a.y, c.y);
        *(float4*)(dst + 2) = make_float4(a.z, c.z, a.w, c.w);
        return;
    }
    int j = i - NX4;
    if (j < NDCN) {
        int k2 = j / (4 * O_ * 8);
        int r  = j % (4 * O_ * 8);
        int q  = r / (O_ * 8);
        int r2 = r % (O_ * 8);
        int o  = r2 / 8;
        int cp = r2 % 8;
        int c  = q * 16 + cp * 2;
        float w0 = w_dcn[(o * C_ + c) * K2C + k2];
        float w1 = w_dcn[(o * C_ + c + 1) * K2C + k2];
        split_store(&g_wq_hi[j], &g_wq_lo[j], w0, w1);
        return;
    }
    j -= NDCN;
    if (j < NOFFW) {
        int k2 = j / (4 * NOFF * 8);
        int r  = j % (4 * NOFF * 8);
        int q  = r / (NOFF * 8);
        int r2 = r % (NOFF * 8);
        int o  = r2 / 8;
        int cp = r2 % 8;
        int c  = q * 16 + cp * 2;
        float w0 = 0.f, w1 = 0.f;
        if (o < OFFC) {
            w0 = w_off[(o * C_ + c) * K2C + k2];
            w1 = w_off[(o * C_ + c + 1) * K2C + k2];
        }
        split_store(&g_wo_hi[j], &g_wo_lo[j], w0, w1);
    }
}

// ---------------------------------------------------------------------------
// Kernel 2: FUSED offset-conv + deformable conv — 512 THREADS per 256-px
// block (same smem/tiles/staging as the proven R12/R15 kernel, but 2x warps
// per SM: 32 warps resident, halved per-thread tiles).
// Sampling: 512 thr = 256 px x 2 chpair-halves (4 chpairs each).
// Phase A GEMM: 16 warps x (16px x 24oc) = 12 acc.
// Phase B GEMM: 16 warps = 4 px-groups x 4 oc-groups, 64px x 16oc = 32 acc.
// ---------------------------------------------------------------------------
__global__ void __launch_bounds__(512, 2) fused_kernel(
    const float* __restrict__ b_off,
    const float* __restrict__ b_dcn,
    float* __restrict__ out)
{
    __shared__ __align__(16) uint32_t smp[2][2][256][9];   // 73.7 KB
    __shared__ __align__(16) uint32_t wsm[2][2][O_][10];   // 20.5 KB
    __shared__ float off_s[OFFC][256];                     // 18 KB

    const int t    = threadIdx.x;
    const int lane = t & 31;
    const int warp = t >> 5;
    const int px   = t & 255;          // sampling pixel 0..255
    const int scg  = t >> 8;           // chpair half (0/1)
    const int ho0  = blockIdx.x * 2;
    const int b    = blockIdx.y;
    const int g  = lane >> 2;
    const int tt = lane & 3;
    const int s_ho = ho0 + (px >> 7);
    const int s_wo = px & 127;

    const float2* xpb = g_xp + (size_t)b * CP_ * HW;

    // ======================= PHASE A: offset conv ==========================
    {
        const int px0 = warp * 16;     // GEMM: 16 px per warp

        auto stage_wo = [&](int buf, int tap, int q) {
            if (t < 192) {
                int h = t >= 96;
                int r = t - h * 96;
                int o = r >> 2, s = r & 3;
                const uint2* src = (const uint2*)((h ? g_wo_lo : g_wo_hi)
                                   + (size_t)((tap * 4 + q) * NOFF * 8));
                uint2 v = __ldg(src + o * 4 + s);
                *(uint2*)&wsm[buf][h][o][2 * s] = v;
            }
        };

        auto sample_o = [&](int buf, int tap, int q) {
            const int dy = tap / 3 - 1, dx = tap % 3 - 1;
            const int cpbase = q * 8 + scg * 4;
            int yy = s_ho + dy, xx = s_wo + dx;
            bool v = (yy >= 0) & (yy < H_) & (xx >= 0) & (xx < W_);
            int off = yy * W_ + xx;
#pragma unroll
            for (int pr = 0; pr < 4; pr++) {
                float2 sv = v ? __ldg(xpb + (size_t)(cpbase + pr) * HW + off)
                              : make_float2(0.f, 0.f);
                split_store(&smp[buf][0][px][scg * 4 + pr],
                            &smp[buf][1][px][scg * 4 + pr], sv.x, sv.y);
            }
        };

        float acc[3][4];
#pragma unroll
        for (int j = 0; j < 3; j++)
#pragma unroll
            for (int k = 0; k < 4; k++) acc[j][k] = 0.f;

        stage_wo(0, 0, 0);
        sample_o(0, 0, 0);
        __syncthreads();

        for (int it = 0; it < 36; it++) {
            const int buf = it & 1;
            if (it < 35) {
                int n = it + 1;
                stage_wo(n & 1, n >> 2, n & 3);
                sample_o(n & 1, n >> 2, n & 3);
            }
            {
                const uint32_t (*sh)[9]  = smp[buf][0];
                const uint32_t (*sl)[9]  = smp[buf][1];
                const uint32_t (*wh)[10] = wsm[buf][0];
                const uint32_t (*wl)[10] = wsm[buf][1];

                int r0 = px0 + g;
                int r1 = r0 + 8;
                uint32_t ah[4] = { sh[r0][tt], sh[r1][tt],
                                   sh[r0][tt + 4], sh[r1][tt + 4] };
                uint32_t al[4] = { sl[r0][tt], sl[r1][tt],
                                   sl[r0][tt + 4], sl[r1][tt + 4] };
#pragma unroll
                for (int oct = 0; oct < 3; oct++) {
                    int orow = oct * 8 + g;
                    uint32_t bh[2] = { wh[orow][tt], wh[orow][tt + 4] };
                    uint32_t bl[2] = { wl[orow][tt], wl[orow][tt + 4] };
                    mma_bf16(acc[oct], ah, bh);
                    mma_bf16(acc[oct], ah, bl);
                    mma_bf16(acc[oct], al, bh);
                }
            }
            __syncthreads();
        }

        // epilogue -> smem offsets
#pragma unroll
        for (int oct = 0; oct < 3; oct++) {
            int oc0 = oct * 8 + 2 * tt;
            if (oc0 < OFFC) {
                float bia0 = __ldg(b_off + oc0);
                float bia1 = (oc0 + 1 < OFFC) ? __ldg(b_off + oc0 + 1) : 0.f;
#pragma unroll
                for (int rr = 0; rr < 2; rr++) {
                    int p = px0 + g + 8 * rr;
                    off_s[oc0][p] = acc[oct][2 * rr + 0] + bia0;
                    if (oc0 + 1 < OFFC)
                        off_s[oc0 + 1][p] = acc[oct][2 * rr + 1] + bia1;
                }
            }
        }
    }
    __syncthreads();

    // ======================= PHASE B: deformable conv ======================
    {
        const int g_px0 = 64 * (warp >> 2);
        const int g_ob  = 16 * (warp & 3);

        auto stage_wd = [&](int buf, int tap, int q) {
            int o = t >> 3;            // 0..63
            int h = (t >> 2) & 1;      // hi/lo
            int s = t & 3;             // uint2 slot
            const uint2* src = (const uint2*)((h ? g_wq_lo : g_wq_hi)
                               + (size_t)((tap * 4 + q) * O_ * 8));
            uint2 v = __ldg(src + o * 4 + s);
            *(uint2*)&wsm[buf][h][o][2 * s] = v;
        };

        float4 mw;
        int4   mo;

        auto compute_meta = [&](int tap) {
            float oy = off_s[2 * tap][px];
            float ox = off_s[2 * tap + 1][px];
            float py  = (float)(s_ho - 1 + tap / 3) + oy;
            float pxx = (float)(s_wo - 1 + tap % 3) + ox;
            float y0f = floorf(py), x0f = floorf(pxx);
            float wy = py - y0f, wx = pxx - x0f;
            int y0 = (int)y0f, x0 = (int)x0f;
            float vy0 = ((y0 >= 0)  & (y0 < H_))     ? 1.f : 0.f;
            float vy1 = ((y0 >= -1) & (y0 < H_ - 1)) ? 1.f : 0.f;
            float vx0 = ((x0 >= 0)  & (x0 < W_))     ? 1.f : 0.f;
            float vx1 = ((x0 >= -1) & (x0 < W_ - 1)) ? 1.f : 0.f;
            mw.x = (1.f - wy) * (1.f - wx) * vy0 * vx0;
            mw.y = (1.f - wy) * wx         * vy0 * vx1;
            mw.z = wy * (1.f - wx)         * vy1 * vx0;
            mw.w = wy * wx                 * vy1 * vx1;
            int y0c = min(max(y0, 0), H_ - 1);
            int y1c = min(max(y0 + 1, 0), H_ - 1);
            int x0c = min(max(x0, 0), W_ - 1);
            int x1c = min(max(x0 + 1, 0), W_ - 1);
            mo.x = y0c * W_ + x0c;
            mo.y = y0c * W_ + x1c;
            mo.z = y1c * W_ + x0c;
            mo.w = y1c * W_ + x1c;
        };

        auto sample_d = [&](int buf, int q) {
            const int cpbase = q * 8 + scg * 4;
#pragma unroll
            for (int pr = 0; pr < 4; pr++) {
                const float2* xc = xpb + (size_t)(cpbase + pr) * HW;
                float2 v00 = __ldg(xc + mo.x);
                float2 v01 = __ldg(xc + mo.y);
                float2 v10 = __ldg(xc + mo.z);
                float2 v11 = __ldg(xc + mo.w);
                float s0 = v00.x * mw.x + v01.x * mw.y
                         + v10.x * mw.z + v11.x * mw.w;
                float s1 = v00.y * mw.x + v01.y * mw.y
                         + v10.y * mw.z + v11.y * mw.w;
                split_store(&smp[buf][0][px][scg * 4 + pr],
                            &smp[buf][1][px][scg * 4 + pr], s0, s1);
            }
        };

        float acc[4][2][4];
#pragma unroll
        for (int i = 0; i < 4; i++)
#pragma unroll
            for (int j = 0; j < 2; j++)
#pragma unroll
                for (int k = 0; k < 4; k++) acc[i][j][k] = 0.f;

        stage_wd(0, 0, 0);
        compute_meta(0);
        sample_d(0, 0);
        __syncthreads();

        for (int it = 0; it < 36; it++) {
            const int buf = it & 1;
            if (it < 35) {
                int n = it + 1;
                stage_wd(n & 1, n >> 2, n & 3);
                if ((n & 3) == 0) compute_meta(n >> 2);
                sample_d(n & 1, n & 3);
            }
            {
                const uint32_t (*sh)[9]  = smp[buf][0];
                const uint32_t (*sl)[9]  = smp[buf][1];
                const uint32_t (*wh)[10] = wsm[buf][0];
                const uint32_t (*wl)[10] = wsm[buf][1];

                uint32_t bh[2][2], bl[2][2];
#pragma unroll
                for (int oct = 0; oct < 2; oct++) {
                    int orow = g_ob + oct * 8 + g;
                    bh[oct][0] = wh[orow][tt];
                    bh[oct][1] = wh[orow][tt + 4];
                    bl[oct][0] = wl[orow][tt];
                    bl[oct][1] = wl[orow][tt + 4];
                }
#pragma unroll
                for (int pxt = 0; pxt < 4; pxt++) {
                    int r0 = g_px0 + pxt * 16 + g;
                    int r1 = r0 + 8;
                    uint32_t ah[4] = { sh[r0][tt], sh[r1][tt],
                                       sh[r0][tt + 4], sh[r1][tt + 4] };
                    uint32_t al[4] = { sl[r0][tt], sl[r1][tt],
                                       sl[r0][tt + 4], sl[r1][tt + 4] };
#pragma unroll
                    for (int oct = 0; oct < 2; oct++) {
                        mma_bf16(acc[pxt][oct], ah, bh[oct]);
                        mma_bf16(acc[pxt][oct], ah, bl[oct]);
                        mma_bf16(acc[pxt][oct], al, bh[oct]);
                    }
                }
            }
            __syncthreads();
        }

#pragma unroll
        for (int oct = 0; oct < 2; oct++) {
            int oc0 = g_ob + oct * 8 + 2 * tt;
            float bia0 = __ldg(b_dcn + oc0);
            float bia1 = __ldg(b_dcn + oc0 + 1);
#pragma unroll
            for (int pxt = 0; pxt < 4; pxt++) {
                int p0 = g_px0 + pxt * 16 + g;
#pragma unroll
                for (int rr = 0; rr < 2; rr++) {
                    int p  = p0 + 8 * rr;
                    int ho = ho0 + (p >> 7);
                    int wo = p & 127;
                    out[(((size_t)b * O_ + oc0)     * H_ + ho) * W_ + wo] =
                        acc[pxt][oct][2 * rr + 0] + bia0;
                    out[(((size_t)b * O_ + oc0 + 1) * H_ + ho) * W_ + wo] =
                        acc[pxt][oct][2 * rr + 1] + bia1;
                }
            }
        }
    }
}

// ---------------------------------------------------------------------------
extern "C" void kernel_launch(void* const* d_in, const int* in_sizes, int n_in,
                              void* d_out, int out_size)
{
    const float* x     = (const float*)d_in[0];
    const float* w_off = (const float*)d_in[1];
    const float* b_off = (const float*)d_in[2];
    const float* w_dcn = (const float*)d_in[3];
    const float* b_dcn = (const float*)d_in[4];
    float* out = (float*)d_out;

    prep_kernel<<<(NX4 + NDCN + NOFFW + 255) / 256, 256>>>(x, w_dcn, w_off);
    fused_kernel<<<dim3(H_ / 2, B_), 512>>>(b_off, b_dcn, out);
}

// round 17
// speedup vs baseline: 1.4304x; 1.4304x over previous
#include <cuda_runtime.h>
#include <cuda_bf16.h>
#include <cuda_fp16.h>
#include <cstdint>

#define B_   4
#define C_   64
#define W_   128
#define H_   128
#define O_   64
#define K2C  9
#define OFFC 18
#define NOFF 24
#define HW   (H_*W_)
#define NCQ  16           // channel quads (64/4)

__device__ __align__(16) uint32_t g_wq_hi[K2C * 4 * O_ * 8];
__device__ __align__(16) uint32_t g_wq_lo[K2C * 4 * O_ * 8];
__device__ __align__(16) uint32_t g_wo_hi[K2C * 4 * NOFF * 8];
__device__ __align__(16) uint32_t g_wo_lo[K2C * 4 * NOFF * 8];
__device__ __align__(16) uint2    g_xq[B_ * NCQ * HW];   // fp16 quads [b][cq][hw]

__device__ __forceinline__ void mma_bf16(float* d, const uint32_t* a,
                                         const uint32_t* b) {
    asm volatile(
        "mma.sync.aligned.m16n8k16.row.col.f32.bf16.bf16.f32 "
        "{%0,%1,%2,%3}, {%4,%5,%6,%7}, {%8,%9}, {%0,%1,%2,%3};"
        : "+f"(d[0]), "+f"(d[1]), "+f"(d[2]), "+f"(d[3])
        : "r"(a[0]), "r"(a[1]), "r"(a[2]), "r"(a[3]),
          "r"(b[0]), "r"(b[1]));
}

__device__ __forceinline__ void split_store(uint32_t* hi, uint32_t* lo,
                                            float s0, float s1) {
    float2 sv = make_float2(s0, s1);
    __nv_bfloat162 h2 = __float22bfloat162_rn(sv);
    float2 hv = make_float2(__bfloat162float(h2.x), __bfloat162float(h2.y));
    __nv_bfloat162 l2 = __float22bfloat162_rn(make_float2(sv.x - hv.x, sv.y - hv.y));
    *hi = *reinterpret_cast<uint32_t*>(&h2);
    *lo = *reinterpret_cast<uint32_t*>(&l2);
}

__device__ __forceinline__ float4 quad_to_float4(uint2 v) {
    __half2 a = *reinterpret_cast<__half2*>(&v.x);
    __half2 b = *reinterpret_cast<__half2*>(&v.y);
    float2 fa = __half22float2(a);
    float2 fb = __half22float2(b);
    return make_float4(fa.x, fa.y, fb.x, fb.y);
}

// ---------------------------------------------------------------------------
// Kernel 1: merged prep — x -> fp16 channel quads (4 px per thread) + both
// weight tensors (bf16 hi/lo split, [k2][q][o][chpair]).
// ---------------------------------------------------------------------------
#define NXQ  (B_ * NCQ * (HW / 4))
#define NDCN (K2C * 4 * O_ * 8)
#define NOFFW (K2C * 4 * NOFF * 8)

__global__ void prep_kernel(const float* __restrict__ x,
                            const float* __restrict__ w_dcn,
                            const float* __restrict__ w_off)
{
    int i = blockIdx.x * 256 + threadIdx.x;
    if (i < NXQ) {
        int b  = i / (NCQ * (HW / 4));
        int r  = i % (NCQ * (HW / 4));
        int cq = r / (HW / 4);
        int s4 = (r % (HW / 4)) * 4;
        const float* base = x + ((size_t)(b * C_ + 4 * cq)) * HW + s4;
        float4 p0 = __ldg((const float4*)(base));
        float4 p1 = __ldg((const float4*)(base + HW));
        float4 p2 = __ldg((const float4*)(base + 2 * HW));
        float4 p3 = __ldg((const float4*)(base + 3 * HW));
        uint2* dst = g_xq + ((size_t)(b * NCQ + cq)) * HW + s4;
        const float* q0 = &p0.x;
        const float* q1 = &p1.x;
        const float* q2 = &p2.x;
        const float* q3 = &p3.x;
#pragma unroll
        for (int j = 0; j < 4; j++) {
            __half2 lo = __floats2half2_rn(q0[j], q1[j]);
            __half2 hi = __floats2half2_rn(q2[j], q3[j]);
            uint2 v;
            v.x = *reinterpret_cast<uint32_t*>(&lo);
            v.y = *reinterpret_cast<uint32_t*>(&hi);
            dst[j] = v;
        }
        return;
    }
    int j = i - NXQ;
    if (j < NDCN) {
        int k2 = j / (4 * O_ * 8);
        int r  = j % (4 * O_ * 8);
        int q  = r / (O_ * 8);
        int r2 = r % (O_ * 8);
        int o  = r2 / 8;
        int cp = r2 % 8;
        int c  = q * 16 + cp * 2;
        float w0 = w_dcn[(o * C_ + c) * K2C + k2];
        float w1 = w_dcn[(o * C_ + c + 1) * K2C + k2];
        split_store(&g_wq_hi[j], &g_wq_lo[j], w0, w1);
        return;
    }
    j -= NDCN;
    if (j < NOFFW) {
        int k2 = j / (4 * NOFF * 8);
        int r  = j % (4 * NOFF * 8);
        int q  = r / (NOFF * 8);
        int r2 = r % (NOFF * 8);
        int o  = r2 / 8;
        int cp = r2 % 8;
        int c  = q * 16 + cp * 2;
        float w0 = 0.f, w1 = 0.f;
        if (o < OFFC) {
            w0 = w_off[(o * C_ + c) * K2C + k2];
            w1 = w_off[(o * C_ + c + 1) * K2C + k2];
        }
        split_store(&g_wo_hi[j], &g_wo_lo[j], w0, w1);
    }
}

// ---------------------------------------------------------------------------
// Kernel 2: FUSED offset-conv + deformable conv (R15 structure; only the
// gather path changed to fp16 channel-quads: half the gather bytes and
// half the gather instructions; bilinear stays fp32).
// ---------------------------------------------------------------------------
__global__ void __launch_bounds__(256, 2) fused_kernel(
    const float* __restrict__ b_off,
    const float* __restrict__ b_dcn,
    float* __restrict__ out)
{
    __shared__ __align__(16) uint32_t smp[2][2][256][9];   // 73.7 KB
    __shared__ __align__(16) uint32_t wsm[2][2][O_][10];   // 20.5 KB
    __shared__ float off_s[OFFC][256];                     // 18 KB

    const int t    = threadIdx.x;
    const int lane = t & 31;
    const int warp = t >> 5;
    const int s_pxg = warp >> 1;
    const int s_cg  = warp & 1;
    const int ho0   = blockIdx.x * 2;
    const int b     = blockIdx.y;
    const int g  = lane >> 2;
    const int tt = lane & 3;

    const uint2* xqb = g_xq + (size_t)b * NCQ * HW;

    // ======================= PHASE A: offset conv ==========================
    {
        const int px0 = warp * 32;

        auto stage_wo = [&](int buf, int tap, int q) {
            if (t < 192) {
                int h = t >= 96;
                int r = t - h * 96;
                int o = r >> 2, s = r & 3;
                const uint2* src = (const uint2*)((h ? g_wo_lo : g_wo_hi)
                                   + (size_t)((tap * 4 + q) * NOFF * 8));
                uint2 v = __ldg(src + o * 4 + s);
                *(uint2*)&wsm[buf][h][o][2 * s] = v;
            }
        };

        auto sample_o = [&](int buf, int tap, int q) {
            const int dy = tap / 3 - 1, dx = tap % 3 - 1;
#pragma unroll
            for (int i = 0; i < 2; i++) {
                int p  = 64 * s_pxg + lane + 32 * i;
                int ho = ho0 + (p >> 7);
                int wo = p & 127;
                int yy = ho + dy, xx = wo + dx;
                bool v = (yy >= 0) & (yy < H_) & (xx >= 0) & (xx < W_);
                int off = yy * W_ + xx;
#pragma unroll
                for (int jq = 0; jq < 2; jq++) {
                    int cq = q * 4 + s_cg * 2 + jq;
                    uint2 raw = v ? __ldg(xqb + (size_t)cq * HW + off)
                                  : make_uint2(0u, 0u);
                    float4 f = quad_to_float4(raw);
                    int cc = s_cg * 4 + 2 * jq;
                    split_store(&smp[buf][0][p][cc],
                                &smp[buf][1][p][cc], f.x, f.y);
                    split_store(&smp[buf][0][p][cc + 1],
                                &smp[buf][1][p][cc + 1], f.z, f.w);
                }
            }
        };

        float acc[2][3][4];
#pragma unroll
        for (int i = 0; i < 2; i++)
#pragma unroll
            for (int j = 0; j < 3; j++)
#pragma unroll
                for (int k = 0; k < 4; k++) acc[i][j][k] = 0.f;

        stage_wo(0, 0, 0);
        sample_o(0, 0, 0);
        __syncthreads();

        for (int it = 0; it < 36; it++) {
            const int buf = it & 1;
            if (it < 35) {
                int n = it + 1;
                stage_wo(n & 1, n >> 2, n & 3);
                sample_o(n & 1, n >> 2, n & 3);
            }
            {
                const uint32_t (*sh)[9]  = smp[buf][0];
                const uint32_t (*sl)[9]  = smp[buf][1];
                const uint32_t (*wh)[10] = wsm[buf][0];
                const uint32_t (*wl)[10] = wsm[buf][1];

                uint32_t bh[3][2], bl[3][2];
#pragma unroll
                for (int oct = 0; oct < 3; oct++) {
                    int orow = oct * 8 + g;
                    bh[oct][0] = wh[orow][tt];
                    bh[oct][1] = wh[orow][tt + 4];
                    bl[oct][0] = wl[orow][tt];
                    bl[oct][1] = wl[orow][tt + 4];
                }
#pragma unroll
                for (int pxt = 0; pxt < 2; pxt++) {
                    int r0 = px0 + pxt * 16 + g;
                    int r1 = r0 + 8;
                    uint32_t ah[4] = { sh[r0][tt], sh[r1][tt],
                                       sh[r0][tt + 4], sh[r1][tt + 4] };
                    uint32_t al[4] = { sl[r0][tt], sl[r1][tt],
                                       sl[r0][tt + 4], sl[r1][tt + 4] };
#pragma unroll
                    for (int oct = 0; oct < 3; oct++) {
                        mma_bf16(acc[pxt][oct], ah, bh[oct]);
                        mma_bf16(acc[pxt][oct], ah, bl[oct]);
                        mma_bf16(acc[pxt][oct], al, bh[oct]);
                    }
                }
            }
            __syncthreads();
        }

#pragma unroll
        for (int oct = 0; oct < 3; oct++) {
            int oc0 = oct * 8 + 2 * tt;
            if (oc0 < OFFC) {
                float bia0 = __ldg(b_off + oc0);
                float bia1 = (oc0 + 1 < OFFC) ? __ldg(b_off + oc0 + 1) : 0.f;
#pragma unroll
                for (int pxt = 0; pxt < 2; pxt++) {
#pragma unroll
                    for (int rr = 0; rr < 2; rr++) {
                        int p = px0 + pxt * 16 + g + 8 * rr;
                        off_s[oc0][p] = acc[pxt][oct][2 * rr + 0] + bia0;
                        if (oc0 + 1 < OFFC)
                            off_s[oc0 + 1][p] = acc[pxt][oct][2 * rr + 1] + bia1;
                    }
                }
            }
        }
    }
    __syncthreads();

    // ======================= PHASE B: deformable conv ======================
    {
        const int g_px0 = 64 * (warp >> 1);
        const int g_ob  = 32 * (warp & 1);

        auto stage_wd = [&](int buf, int tap, int q) {
            const uint2* srch = (const uint2*)(g_wq_hi + (size_t)((tap * 4 + q) * O_ * 8));
            const uint2* srcl = (const uint2*)(g_wq_lo + (size_t)((tap * 4 + q) * O_ * 8));
            int o = t >> 2, s = t & 3;
            uint2 vh = __ldg(srch + o * 4 + s);
            uint2 vl = __ldg(srcl + o * 4 + s);
            *(uint2*)&wsm[buf][0][o][2 * s] = vh;
            *(uint2*)&wsm[buf][1][o][2 * s] = vl;
        };

        float4 mw[2];
        int4   mo[2];

        auto compute_meta = [&](int tap) {
#pragma unroll
            for (int i = 0; i < 2; i++) {
                int p  = 64 * s_pxg + lane + 32 * i;
                int ho = ho0 + (p >> 7);
                int wo = p & 127;
                float oy = off_s[2 * tap][p];
                float ox = off_s[2 * tap + 1][p];
                float py = (float)(ho - 1 + tap / 3) + oy;
                float px = (float)(wo - 1 + tap % 3) + ox;
                float y0f = floorf(py), x0f = floorf(px);
                float wy = py - y0f, wx = px - x0f;
                int y0 = (int)y0f, x0 = (int)x0f;
                float vy0 = ((y0 >= 0)  & (y0 < H_))     ? 1.f : 0.f;
                float vy1 = ((y0 >= -1) & (y0 < H_ - 1)) ? 1.f : 0.f;
                float vx0 = ((x0 >= 0)  & (x0 < W_))     ? 1.f : 0.f;
                float vx1 = ((x0 >= -1) & (x0 < W_ - 1)) ? 1.f : 0.f;
                mw[i].x = (1.f - wy) * (1.f - wx) * vy0 * vx0;
                mw[i].y = (1.f - wy) * wx         * vy0 * vx1;
                mw[i].z = wy * (1.f - wx)         * vy1 * vx0;
                mw[i].w = wy * wx                 * vy1 * vx1;
                int y0c = min(max(y0, 0), H_ - 1);
                int y1c = min(max(y0 + 1, 0), H_ - 1);
                int x0c = min(max(x0, 0), W_ - 1);
                int x1c = min(max(x0 + 1, 0), W_ - 1);
                mo[i].x = y0c * W_ + x0c;
                mo[i].y = y0c * W_ + x1c;
                mo[i].z = y1c * W_ + x0c;
                mo[i].w = y1c * W_ + x1c;
            }
        };

        auto sample_d = [&](int buf, int q) {
#pragma unroll
            for (int i = 0; i < 2; i++) {
                int p = 64 * s_pxg + lane + 32 * i;
#pragma unroll
                for (int jq = 0; jq < 2; jq++) {
                    int cq = q * 4 + s_cg * 2 + jq;
                    const uint2* xc = xqb + (size_t)cq * HW;
                    float4 f00 = quad_to_float4(__ldg(xc + mo[i].x));
                    float4 f01 = quad_to_float4(__ldg(xc + mo[i].y));
                    float4 f10 = quad_to_float4(__ldg(xc + mo[i].z));
                    float4 f11 = quad_to_float4(__ldg(xc + mo[i].w));
                    float s0 = f00.x * mw[i].x + f01.x * mw[i].y
                             + f10.x * mw[i].z + f11.x * mw[i].w;
                    float s1 = f00.y * mw[i].x + f01.y * mw[i].y
                             + f10.y * mw[i].z + f11.y * mw[i].w;
                    float s2 = f00.z * mw[i].x + f01.z * mw[i].y
                             + f10.z * mw[i].z + f11.z * mw[i].w;
                    float s3 = f00.w * mw[i].x + f01.w * mw[i].y
                             + f10.w * mw[i].z + f11.w * mw[i].w;
                    int cc = s_cg * 4 + 2 * jq;
                    split_store(&smp[buf][0][p][cc],
                                &smp[buf][1][p][cc], s0, s1);
                    split_store(&smp[buf][0][p][cc + 1],
                                &smp[buf][1][p][cc + 1], s2, s3);
                }
            }
        };

        float acc[4][4][4];
#pragma unroll
        for (int i = 0; i < 4; i++)
#pragma unroll
            for (int j = 0; j < 4; j++)
#pragma unroll
                for (int k = 0; k < 4; k++) acc[i][j][k] = 0.f;

        stage_wd(0, 0, 0);
        compute_meta(0);
        sample_d(0, 0);
        __syncthreads();

        for (int it = 0; it < 36; it++) {
            const int buf = it & 1;
            if (it < 35) {
                int n = it + 1;
                stage_wd(n & 1, n >> 2, n & 3);
                if ((n & 3) == 0) compute_meta(n >> 2);
                sample_d(n & 1, n & 3);
            }
            {
                const uint32_t (*sh)[9]  = smp[buf][0];
                const uint32_t (*sl)[9]  = smp[buf][1];
                const uint32_t (*wh)[10] = wsm[buf][0];
                const uint32_t (*wl)[10] = wsm[buf][1];

                uint32_t bh[4][2], bl[4][2];
#pragma unroll
                for (int oct = 0; oct < 4; oct++) {
                    int orow = g_ob + oct * 8 + g;
                    bh[oct][0] = wh[orow][tt];
                    bh[oct][1] = wh[orow][tt + 4];
                    bl[oct][0] = wl[orow][tt];
                    bl[oct][1] = wl[orow][tt + 4];
                }
#pragma unroll
                for (int pxt = 0; pxt < 4; pxt++) {
                    int r0 = g_px0 + pxt * 16 + g;
                    int r1 = r0 + 8;
                    uint32_t ah[4] = { sh[r0][tt], sh[r1][tt],
                                       sh[r0][tt + 4], sh[r1][tt + 4] };
                    uint32_t al[4] = { sl[r0][tt], sl[r1][tt],
                                       sl[r0][tt + 4], sl[r1][tt + 4] };
#pragma unroll
                    for (int oct = 0; oct < 4; oct++) {
                        mma_bf16(acc[pxt][oct], ah, bh[oct]);
                        mma_bf16(acc[pxt][oct], ah, bl[oct]);
                        mma_bf16(acc[pxt][oct], al, bh[oct]);
                    }
                }
            }
            __syncthreads();
        }

#pragma unroll
        for (int oct = 0; oct < 4; oct++) {
            int oc0 = g_ob + oct * 8 + 2 * tt;
            float bia0 = __ldg(b_dcn + oc0);
            float bia1 = __ldg(b_dcn + oc0 + 1);
#pragma unroll
            for (int pxt = 0; pxt < 4; pxt++) {
                int p0 = g_px0 + pxt * 16 + g;
#pragma unroll
                for (int rr = 0; rr < 2; rr++) {
                    int p  = p0 + 8 * rr;
                    int ho = ho0 + (p >> 7);
                    int wo = p & 127;
                    out[(((size_t)b * O_ + oc0)     * H_ + ho) * W_ + wo] =
                        acc[pxt][oct][2 * rr + 0] + bia0;
                    out[(((size_t)b * O_ + oc0 + 1) * H_ + ho) * W_ + wo] =
                        acc[pxt][oct][2 * rr + 1] + bia1;
                }
            }
        }
    }
}

// ---------------------------------------------------------------------------
extern "C" void kernel_launch(void* const* d_in, const int* in_sizes, int n_in,
                              void* d_out, int out_size)
{
    const float* x     = (const float*)d_in[0];
    const float* w_off = (const float*)d_in[1];
    const float* b_off = (const float*)d_in[2];
    const float* w_dcn = (const float*)d_in[3];
    const float* b_dcn = (const float*)d_in[4];
    float* out = (float*)d_out;

    prep_kernel<<<(NXQ + NDCN + NOFFW + 255) / 256, 256>>>(x, w_dcn, w_off);
    fused_kernel<<<dim3(H_ / 2, B_), 256>>>(b_off, b_dcn, out);
}